// round 11
// baseline (speedup 1.0000x reference)
#include <cuda_runtime.h>
#include <cuda_bf16.h>
#include <math.h>
#include <stdint.h>

#define BB 64
#define SS 512
#define HH 1024
#define TT 24
#define NROWS (BB*SS)

#define GRID 296
#define NTH 512                    // 16 warps = 8 pairs
#define NWARP 16
#define NPAIR 8
#define NTILES (NROWS/16)          // 2048 tiles of 16 rows
#define PW 1032                    // W smem pitch in bf16 (conflict-free)

// ---- smem layout (bytes) ----
#define WHI_OFF 0
#define WLO_OFF 49536              // 24*1032*2
#define SB_OFF  99072
#define SRED_OFF (99072+128)
#define SPAIR_OFF (99072+256)      // 8 pairs * 1536
#define SMEM_TOTAL (SPAIR_OFF + NPAIR*1536)   // 111616 (x2 CTAs = 223232 <= 228KB)

// ---------------- device scratch ----------------
__device__ float    g_loss_sum;
__device__ unsigned g_ticket;
__device__ unsigned g_tile;

__device__ __forceinline__ float neg_inf() { return __int_as_float(0xff800000); }

__device__ __forceinline__ uint32_t packbf(float x, float y) {
    uint32_t r; asm("cvt.rn.bf16x2.f32 %0, %1, %2;" : "=r"(r) : "f"(y), "f"(x)); return r;
}
__device__ __forceinline__ void split2f(float x, float y, uint32_t& hi, uint32_t& lo) {
    hi = packbf(x, y);
    float rx = x - __uint_as_float(hi << 16);
    float ry = y - __uint_as_float(hi & 0xFFFF0000u);
    lo = packbf(rx, ry);
}

__device__ __forceinline__ void mma16816(float* c, const uint32_t* a, uint32_t b0, uint32_t b1) {
    asm volatile("mma.sync.aligned.m16n8k16.row.col.f32.bf16.bf16.f32 "
        "{%0,%1,%2,%3}, {%4,%5,%6,%7}, {%8,%9}, {%0,%1,%2,%3};"
        : "+f"(c[0]), "+f"(c[1]), "+f"(c[2]), "+f"(c[3])
        : "r"(a[0]), "r"(a[1]), "r"(a[2]), "r"(a[3]), "r"(b0), "r"(b1));
}

__device__ __forceinline__ int getmask(const void* p, int mt, long i) {
    return mt == 0 ? (((const unsigned char*)p)[i] != 0)
         : mt == 1 ? (((const float*)p)[i] != 0.0f)
                   : (((const int*)p)[i] != 0);
}

// ================= single fused kernel =================
__global__ void __launch_bounds__(NTH, 2)
crf_kernel(const float* __restrict__ feats, const float* __restrict__ W,
           const float* __restrict__ bias, const int* __restrict__ target,
           const void* __restrict__ mask_raw, const float* __restrict__ trans,
           float* __restrict__ out, int has_loss) {
    extern __shared__ unsigned char smem[];
    float* sb   = (float*)(smem + SB_OFF);
    float* sred = (float*)(smem + SRED_OFF);
    __shared__ unsigned s_pairtile[NPAIR];
    __shared__ int   s_flag, s_nz;
    __shared__ float s_tot;

    const int tid = threadIdx.x, warp = tid >> 5, lane = tid & 31;
    const int pair = warp >> 1, p = warp & 1;     // p: K-half parity
    const int r = lane >> 2, kp = lane & 3;
    float* emis = out + has_loss;                 // 4B-aligned only: scalar stores

    // ---- stage + split W with in-chunk k-permutation ----
    for (int i = tid; i < TT * 256; i += NTH) {
        int n = i >> 8, f4i = i & 255;
        int c = f4i >> 2, q = f4i & 3;
        float4 v = ((const float4*)W)[n * 256 + f4i];
        uint32_t h0, l0, h1, l1;
        split2f(v.x, v.y, h0, l0);
        split2f(v.z, v.w, h1, l1);
        unsigned base = (unsigned)(n * PW + c * 16) * 2;
        *(uint32_t*)(smem + WHI_OFF + base + q * 4)      = h0;
        *(uint32_t*)(smem + WHI_OFF + base + 16 + q * 4) = h1;
        *(uint32_t*)(smem + WLO_OFF + base + q * 4)      = l0;
        *(uint32_t*)(smem + WLO_OFF + base + 16 + q * 4) = l1;
    }
    if (tid < TT) sb[tid] = bias[tid];
    if (tid < NWARP) sred[tid] = 0.0f;
    if (tid == 0) { s_flag = 0; s_nz = 0; s_tot = 0.0f; }
    __syncthreads();

    const unsigned u0 = *(const unsigned*)mask_raw;
    const int mt_ = (u0 == 0x01010101u) ? 0 : ((u0 == 0x3F800000u) ? 1 : 2);

    const float4* f4g = (const float4*)feats;
    const unsigned bq = (unsigned)(r * PW + kp * 2) * 2;
    float* spair = (float*)(smem + SPAIR_OFF + pair * 1536);   // [2][32][6]
    const int barid = 1 + pair;    // named barriers 1..8 (0 reserved for __syncthreads)
    float contrib = 0.0f;

    // ---- pair tile-steal loop ----
    for (;;) {
        if (p == 0 && lane == 0) s_pairtile[pair] = atomicAdd(&g_tile, 1u);
        asm volatile("bar.sync %0, 64;" :: "r"(barid) : "memory");
        const unsigned tile = s_pairtile[pair];
        if (tile >= NTILES) break;
        const long row0 = (long)tile * 16;

        const long ra = (row0 + r)     * 256 + kp;   // float4 units
        const long rb = (row0 + r + 8) * 256 + kp;
        const int cbase = p * 32;                    // this warp's K half

        float acc[3][4];
        #pragma unroll
        for (int nt = 0; nt < 3; nt++)
            #pragma unroll
            for (int q = 0; q < 4; q++) acc[nt][q] = 0.0f;

        float4 bA[2], bB[2], bC[2];

        #define LOADC(buf, c) do { \
            buf[0] = __ldcs(f4g + ra + (c) * 4); \
            buf[1] = __ldcs(f4g + rb + (c) * 4); \
        } while (0)

        #define COMPUTE(buf, ch) do { \
            uint32_t ahi[4], alo[4]; \
            split2f(buf[0].x, buf[0].y, ahi[0], alo[0]); \
            split2f(buf[1].x, buf[1].y, ahi[1], alo[1]); \
            split2f(buf[0].z, buf[0].w, ahi[2], alo[2]); \
            split2f(buf[1].z, buf[1].w, ahi[3], alo[3]); \
            const unsigned cb = bq + (unsigned)(ch) * 32; \
            _Pragma("unroll") \
            for (int nt = 0; nt < 3; nt++) { \
                const unsigned o = cb + (unsigned)nt * (8 * PW * 2); \
                uint32_t bh0 = *(const uint32_t*)(smem + WHI_OFF + o); \
                uint32_t bh1 = *(const uint32_t*)(smem + WHI_OFF + o + 16); \
                uint32_t bl0 = *(const uint32_t*)(smem + WLO_OFF + o); \
                uint32_t bl1 = *(const uint32_t*)(smem + WLO_OFF + o + 16); \
                mma16816(acc[nt], ahi, bh0, bh1); \
                mma16816(acc[nt], ahi, bl0, bl1); \
                mma16816(acc[nt], alo, bh0, bh1); \
            } \
        } while (0)

        LOADC(bA, cbase);
        LOADC(bB, cbase + 1);
        #pragma unroll 1
        for (int c = cbase; c < cbase + 30; c += 3) {
            LOADC(bC, c + 2); COMPUTE(bA, c);
            LOADC(bA, c + 3); COMPUTE(bB, c + 1);
            LOADC(bB, c + 4); COMPUTE(bC, c + 2);
        }
        COMPUTE(bA, cbase + 30);
        COMPUTE(bB, cbase + 31);
        #undef LOADC
        #undef COMPUTE

        // ---- exchange K-half partials within the pair ----
        // even warp keeps q0,q1 (rows 0-7): sends q2,q3 ; odd keeps q2,q3: sends q0,q1
        {
            float* myslot = spair + p * 192 + lane * 6;
            const int sq = p ? 0 : 2;     // which q's I send
            #pragma unroll
            for (int nt = 0; nt < 3; nt++) {
                myslot[nt * 2]     = acc[nt][sq];
                myslot[nt * 2 + 1] = acc[nt][sq + 1];
            }
        }
        asm volatile("bar.sync %0, 64;" :: "r"(barid) : "memory");
        {
            const float* other = spair + (p ^ 1) * 192 + lane * 6;
            const int mq = p ? 2 : 0;     // which q's I keep/epilogue
            #pragma unroll
            for (int nt = 0; nt < 3; nt++) {
                acc[nt][mq]     += other[nt * 2];
                acc[nt][mq + 1] += other[nt * 2 + 1];
            }
        }

        // ---- epilogue: this warp handles 8 rows (row0 + p*8 + r) ----
        {
            const long row = row0 + p * 8 + r;
            const int mq = p ? 2 : 0;
            float e[6];
            float* eo = emis + row * TT;
            #pragma unroll
            for (int nt = 0; nt < 3; nt++) {
                const int col = nt * 8 + kp * 2;
                e[nt * 2]     = acc[nt][mq]     + sb[col];
                e[nt * 2 + 1] = acc[nt][mq + 1] + sb[col + 1];
                eo[col]     = e[nt * 2];
                eo[col + 1] = e[nt * 2 + 1];
            }
            float mx = e[0];
            #pragma unroll
            for (int q = 1; q < 6; q++) mx = fmaxf(mx, e[q]);
            mx = fmaxf(mx, __shfl_xor_sync(0xffffffffu, mx, 1));
            mx = fmaxf(mx, __shfl_xor_sync(0xffffffffu, mx, 2));
            float ex = 0.0f;
            #pragma unroll
            for (int q = 0; q < 6; q++) ex += __expf(e[q] - mx);
            const int tg = target[row];
            float sc = 0.0f;
            #pragma unroll
            for (int nt = 0; nt < 3; nt++) {
                const int col = nt * 8 + kp * 2;
                sc += (tg == col) ? e[nt * 2] : 0.0f;
                sc += (tg == col + 1) ? e[nt * 2 + 1] : 0.0f;
            }
            ex += __shfl_xor_sync(0xffffffffu, ex, 1);
            sc += __shfl_xor_sync(0xffffffffu, sc, 1);
            ex += __shfl_xor_sync(0xffffffffu, ex, 2);
            sc += __shfl_xor_sync(0xffffffffu, sc, 2);
            if (kp == 0) {
                const float lse = mx + __logf(ex);
                const int s  = (int)(row & (SS - 1));
                const int mk = getmask(mask_raw, mt_, row);
                contrib += mk ? (sc - lse) : (s == 0 ? -lse : 0.0f);
            }
        }
        // next iteration's bar.sync (tile fetch) orders spair reuse
    }

    // ---- warp + block reduce, ticket ----
    contrib += __shfl_xor_sync(0xffffffffu, contrib, 16);
    contrib += __shfl_xor_sync(0xffffffffu, contrib, 8);
    contrib += __shfl_xor_sync(0xffffffffu, contrib, 4);
    contrib += __shfl_xor_sync(0xffffffffu, contrib, 2);
    contrib += __shfl_xor_sync(0xffffffffu, contrib, 1);
    if (lane == 0) sred[warp] = contrib;
    __syncthreads();
    if (tid == 0) {
        float part = 0.0f;
        #pragma unroll
        for (int w = 0; w < NWARP; w++) part += sred[w];
        atomicAdd(&g_loss_sum, part);
        __threadfence();
        unsigned tk = atomicAdd(&g_ticket, 1u);
        s_flag = (tk == GRID - 1);
    }
    __syncthreads();
    if (!s_flag) return;

    // ================= last block: finalize =================
    float* st = (float*)(smem + SPAIR_OFF);   // transition [576]
    float* sp = st + 576;                      // per-warp scan state [16][24]
    {
        int lnz = 0;
        for (int i = tid; i < TT * TT; i += NTH) {
            float v = trans[i];
            st[i] = v;
            lnz |= (v != 0.0f);
        }
        if (lnz) atomicOr(&s_nz, 1);
    }
    __syncthreads();

    if (!s_nz) {
        if (tid == 0) {
            if (has_loss) out[0] = -g_loss_sum / (float)BB;
            g_loss_sum = 0.0f;
            g_ticket = 0u;
            g_tile = 0u;
        }
        return;
    }

    // generic nonzero-transition path (not taken for this dataset)
    {
        float wsum = 0.0f;
        float* msp = sp + warp * TT;
        for (int b = warp; b < BB; b += NWARP) {
            float sum = 0.0f;
            for (int s = lane; s < SS; s += 32) {
                const long idx = (long)b * SS + s;
                if (getmask(mask_raw, mt_, idx)) {
                    float v = emis[idx * TT + target[idx]];
                    if (s > 0) v += st[target[idx - 1] * TT + target[idx]];
                    sum += v;
                }
            }
            sum += __shfl_xor_sync(0xffffffffu, sum, 16);
            sum += __shfl_xor_sync(0xffffffffu, sum, 8);
            sum += __shfl_xor_sync(0xffffffffu, sum, 4);
            sum += __shfl_xor_sync(0xffffffffu, sum, 2);
            sum += __shfl_xor_sync(0xffffffffu, sum, 1);

            if (lane < TT) msp[lane] = emis[(long)b * SS * TT + lane];
            __syncwarp();
            for (int s = 1; s < SS; s++) {
                if (getmask(mask_raw, mt_, (long)b * SS + s)) {
                    float nv = 0.0f;
                    if (lane < TT) {
                        float mm = neg_inf();
                        #pragma unroll
                        for (int j = 0; j < TT; j++) mm = fmaxf(mm, msp[j] + st[j * TT + lane]);
                        float a = 0.0f;
                        #pragma unroll
                        for (int j = 0; j < TT; j++) a += __expf(msp[j] + st[j * TT + lane] - mm);
                        nv = emis[((long)b * SS + s) * TT + lane] + mm + __logf(a);
                    }
                    __syncwarp();
                    if (lane < TT) msp[lane] = nv;
                    __syncwarp();
                }
            }
            float e2 = (lane < TT) ? msp[lane] : neg_inf();
            float mm = e2;
            mm = fmaxf(mm, __shfl_xor_sync(0xffffffffu, mm, 16));
            mm = fmaxf(mm, __shfl_xor_sync(0xffffffffu, mm, 8));
            mm = fmaxf(mm, __shfl_xor_sync(0xffffffffu, mm, 4));
            mm = fmaxf(mm, __shfl_xor_sync(0xffffffffu, mm, 2));
            mm = fmaxf(mm, __shfl_xor_sync(0xffffffffu, mm, 1));
            float ex2 = (lane < TT) ? __expf(e2 - mm) : 0.0f;
            ex2 += __shfl_xor_sync(0xffffffffu, ex2, 16);
            ex2 += __shfl_xor_sync(0xffffffffu, ex2, 8);
            ex2 += __shfl_xor_sync(0xffffffffu, ex2, 4);
            ex2 += __shfl_xor_sync(0xffffffffu, ex2, 2);
            ex2 += __shfl_xor_sync(0xffffffffu, ex2, 1);
            if (lane == 0) wsum += sum - (mm + __logf(ex2));
        }
        if (lane == 0) atomicAdd(&s_tot, wsum);
    }
    __syncthreads();
    if (tid == 0) {
        if (has_loss) out[0] = -s_tot / (float)BB;
        g_loss_sum = 0.0f;
        g_ticket = 0u;
        g_tile = 0u;
    }
}

// ---------------- launch ----------------
extern "C" void kernel_launch(void* const* d_in, const int* in_sizes, int n_in,
                              void* d_out, int out_size) {
    const float* feats  = (const float*)d_in[0];   // (B,S,H)
    const int*   target = (const int*)d_in[1];     // (B,S)
    const void*  mask   = d_in[2];                 // (B,S) dtype auto-detected
    const float* W      = (const float*)d_in[3];   // (T,H)
    const float* bias   = (const float*)d_in[4];   // (T,)
    const float* trans  = (const float*)d_in[5];   // (T,T)

    float* out = (float*)d_out;
    const int has_loss = (out_size == NROWS * TT + 1) ? 1 : 0;

    static int attr_set = 0;
    if (!attr_set) {
        cudaFuncSetAttribute(crf_kernel, cudaFuncAttributeMaxDynamicSharedMemorySize, SMEM_TOTAL);
        attr_set = 1;
    }

    crf_kernel<<<GRID, NTH, SMEM_TOTAL>>>(feats, W, bias, target, mask, trans, out, has_loss);
}

// round 12
// speedup vs baseline: 1.2108x; 1.2108x over previous
#include <cuda_runtime.h>
#include <cuda_bf16.h>
#include <math.h>
#include <stdint.h>

#define BB 64
#define SS 512
#define HH 1024
#define TT 24
#define NROWS (BB*SS)

#define TILE 256
#define GRID (NROWS/TILE)          // 128 CTAs, one tile each
#define NTH 512                    // 16 warps, warp owns 16 rows
#define NWARP 16
#define NST 32                     // K stages of 32 floats
#define RING 3
#define STAGE_BYTES 32768          // 256 rows * 128 B
#define PW 1032                    // W smem pitch in bf16 (conflict-free)

// ---- smem layout (bytes) ----
#define WHI_OFF 0
#define WLO_OFF 49536              // 24*1032*2
#define SB_OFF  99072
#define SRED_OFF (99072+128)
#define FBUF_OFF (99072+256)
#define SMEM_TOTAL (FBUF_OFF + RING*STAGE_BYTES)   // 197632

// ---------------- device scratch ----------------
__device__ float    g_loss_sum;
__device__ unsigned g_ticket;

__device__ __forceinline__ float neg_inf() { return __int_as_float(0xff800000); }

__device__ __forceinline__ uint32_t packbf(float x, float y) {
    uint32_t r; asm("cvt.rn.bf16x2.f32 %0, %1, %2;" : "=r"(r) : "f"(y), "f"(x)); return r;
}
__device__ __forceinline__ void split2f(float x, float y, uint32_t& hi, uint32_t& lo) {
    hi = packbf(x, y);
    float rx = x - __uint_as_float(hi << 16);
    float ry = y - __uint_as_float(hi & 0xFFFF0000u);
    lo = packbf(rx, ry);
}

__device__ __forceinline__ void mma16816(float* c, const uint32_t* a, uint32_t b0, uint32_t b1) {
    asm volatile("mma.sync.aligned.m16n8k16.row.col.f32.bf16.bf16.f32 "
        "{%0,%1,%2,%3}, {%4,%5,%6,%7}, {%8,%9}, {%0,%1,%2,%3};"
        : "+f"(c[0]), "+f"(c[1]), "+f"(c[2]), "+f"(c[3])
        : "r"(a[0]), "r"(a[1]), "r"(a[2]), "r"(a[3]), "r"(b0), "r"(b1));
}

__device__ __forceinline__ void cp_async16(unsigned s, const void* g) {
    asm volatile("cp.async.cg.shared.global [%0], [%1], 16;" :: "r"(s), "l"(g));
}
#define CP_COMMIT() asm volatile("cp.async.commit_group;")
#define CP_WAIT1()  asm volatile("cp.async.wait_group 1;")

__device__ __forceinline__ int getmask(const void* p, int mt, long i) {
    return mt == 0 ? (((const unsigned char*)p)[i] != 0)
         : mt == 1 ? (((const float*)p)[i] != 0.0f)
                   : (((const int*)p)[i] != 0);
}

// ================= single fused kernel =================
__global__ void __launch_bounds__(NTH, 1)
crf_kernel(const float* __restrict__ feats, const float* __restrict__ W,
           const float* __restrict__ bias, const int* __restrict__ target,
           const void* __restrict__ mask_raw, const float* __restrict__ trans,
           float* __restrict__ out, int has_loss) {
    extern __shared__ unsigned char smem[];
    float* sb   = (float*)(smem + SB_OFF);
    float* sred = (float*)(smem + SRED_OFF);
    __shared__ int   s_flag, s_nz;
    __shared__ float s_tot;

    const int tid = threadIdx.x, warp = tid >> 5, lane = tid & 31;
    const int r = lane >> 2, kp = lane & 3;
    float* emis = out + has_loss;    // 4B-aligned only: scalar stores
    const float4* f4g = (const float4*)feats;
    const long row0 = (long)blockIdx.x * TILE;

    unsigned fb32;
    {
        unsigned char* rb = smem + FBUF_OFF;
        asm("{ .reg .u64 t; cvta.to.shared.u64 t, %1; cvt.u32.u64 %0, t; }"
            : "=r"(fb32) : "l"(rb));
    }

    // issue one 32KB stage (k-chunk c of 32 floats) into ring buffer buf
    #define ISSUE(c, buf) do { \
        unsigned sdst = fb32 + (unsigned)(buf) * STAGE_BYTES; \
        _Pragma("unroll") \
        for (int j = 0; j < 4; j++) { \
            int u = tid + j * NTH; \
            int row = u >> 3, kc = u & 7; \
            int pk = kc ^ ((row & 1) << 2); \
            cp_async16(sdst + (unsigned)(row * 128 + pk * 16), \
                       f4g + (row0 + row) * 256 + (c) * 8 + kc); \
        } \
    } while (0)

    // prologue: stages 0,1 in flight before anything else
    ISSUE(0, 0); CP_COMMIT();
    ISSUE(1, 1); CP_COMMIT();

    // ---- stage + split W with in-chunk k-permutation ----
    for (int i = tid; i < TT * 256; i += NTH) {
        int n = i >> 8, f4i = i & 255;
        int c = f4i >> 2, q = f4i & 3;
        float4 v = ((const float4*)W)[n * 256 + f4i];
        uint32_t h0, l0, h1, l1;
        split2f(v.x, v.y, h0, l0);
        split2f(v.z, v.w, h1, l1);
        unsigned base = (unsigned)(n * PW + c * 16) * 2;
        *(uint32_t*)(smem + WHI_OFF + base + q * 4)      = h0;
        *(uint32_t*)(smem + WHI_OFF + base + 16 + q * 4) = h1;
        *(uint32_t*)(smem + WLO_OFF + base + q * 4)      = l0;
        *(uint32_t*)(smem + WLO_OFF + base + 16 + q * 4) = l1;
    }
    if (tid < TT) sb[tid] = bias[tid];
    if (tid < NWARP) sred[tid] = 0.0f;
    if (tid == 0) { s_flag = 0; s_nz = 0; s_tot = 0.0f; }
    __syncthreads();

    const unsigned u0 = *(const unsigned*)mask_raw;
    const int mt_ = (u0 == 0x01010101u) ? 0 : ((u0 == 0x3F800000u) ? 1 : 2);
    const unsigned bq = (unsigned)(r * PW + kp * 2) * 2;

    float acc[3][4];
    #pragma unroll
    for (int nt = 0; nt < 3; nt++)
        #pragma unroll
        for (int q = 0; q < 4; q++) acc[nt][q] = 0.0f;

    const int myrow0 = warp * 16 + r;        // smem tile row of fragment half 0
    const int rpar = (r & 1) << 2;           // swizzle term (same for row, row+8)

    // ---- main pipelined K loop: 32 stages ----
    #pragma unroll 1
    for (int c = 0; c < NST; c++) {
        CP_WAIT1();          // my groups for stage c complete
        __syncthreads();     // => all threads' data for stage c is in smem
        const unsigned sbase = fb32 + (unsigned)(c % RING) * STAGE_BYTES;

        #pragma unroll
        for (int ck = 0; ck < 2; ck++) {
            const unsigned ubyte = (unsigned)(((ck * 4 + kp) ^ rpar) * 16);
            float4 a0, a1;
            asm volatile("ld.shared.v4.f32 {%0,%1,%2,%3}, [%4];"
                : "=f"(a0.x), "=f"(a0.y), "=f"(a0.z), "=f"(a0.w)
                : "r"(sbase + (unsigned)(myrow0 * 128) + ubyte));
            asm volatile("ld.shared.v4.f32 {%0,%1,%2,%3}, [%4];"
                : "=f"(a1.x), "=f"(a1.y), "=f"(a1.z), "=f"(a1.w)
                : "r"(sbase + (unsigned)((myrow0 + 8) * 128) + ubyte));

            uint32_t ahi[4], alo[4];
            split2f(a0.x, a0.y, ahi[0], alo[0]);
            split2f(a1.x, a1.y, ahi[1], alo[1]);
            split2f(a0.z, a0.w, ahi[2], alo[2]);
            split2f(a1.z, a1.w, ahi[3], alo[3]);

            const unsigned cb = bq + (unsigned)(c * 2 + ck) * 32;
            #pragma unroll
            for (int nt = 0; nt < 3; nt++) {
                const unsigned o = cb + (unsigned)nt * (8 * PW * 2);
                uint32_t bh0 = *(const uint32_t*)(smem + WHI_OFF + o);
                uint32_t bh1 = *(const uint32_t*)(smem + WHI_OFF + o + 16);
                uint32_t bl0 = *(const uint32_t*)(smem + WLO_OFF + o);
                uint32_t bl1 = *(const uint32_t*)(smem + WLO_OFF + o + 16);
                mma16816(acc[nt], ahi, bh0, bh1);
                mma16816(acc[nt], ahi, bl0, bl1);
                mma16816(acc[nt], alo, bh0, bh1);
            }
        }

        if (c + 2 < NST) ISSUE(c + 2, (c + 2) % RING);
        CP_COMMIT();         // commit EVERY iteration (keeps wait counting uniform)
    }
    #undef ISSUE

    // ---- epilogue: bias, scalar emission stores, quad-shfl LSE + target ----
    float contrib = 0.0f;
    #pragma unroll
    for (int rr = 0; rr < 2; rr++) {
        const long row = row0 + warp * 16 + rr * 8 + r;
        float e[6];
        float* eo = emis + row * TT;
        #pragma unroll
        for (int nt = 0; nt < 3; nt++) {
            const int col = nt * 8 + kp * 2;
            e[nt * 2]     = acc[nt][rr * 2]     + sb[col];
            e[nt * 2 + 1] = acc[nt][rr * 2 + 1] + sb[col + 1];
            eo[col]     = e[nt * 2];
            eo[col + 1] = e[nt * 2 + 1];
        }
        float mx = e[0];
        #pragma unroll
        for (int q = 1; q < 6; q++) mx = fmaxf(mx, e[q]);
        mx = fmaxf(mx, __shfl_xor_sync(0xffffffffu, mx, 1));
        mx = fmaxf(mx, __shfl_xor_sync(0xffffffffu, mx, 2));
        float ex = 0.0f;
        #pragma unroll
        for (int q = 0; q < 6; q++) ex += __expf(e[q] - mx);
        const int tg = target[row];
        float sc = 0.0f;
        #pragma unroll
        for (int nt = 0; nt < 3; nt++) {
            const int col = nt * 8 + kp * 2;
            sc += (tg == col) ? e[nt * 2] : 0.0f;
            sc += (tg == col + 1) ? e[nt * 2 + 1] : 0.0f;
        }
        ex += __shfl_xor_sync(0xffffffffu, ex, 1);
        sc += __shfl_xor_sync(0xffffffffu, sc, 1);
        ex += __shfl_xor_sync(0xffffffffu, ex, 2);
        sc += __shfl_xor_sync(0xffffffffu, sc, 2);
        if (kp == 0) {
            const float lse = mx + __logf(ex);
            const int s  = (int)(row & (SS - 1));
            const int mk = getmask(mask_raw, mt_, row);
            contrib += mk ? (sc - lse) : (s == 0 ? -lse : 0.0f);
        }
    }

    // ---- warp + block reduce, ticket ----
    contrib += __shfl_xor_sync(0xffffffffu, contrib, 16);
    contrib += __shfl_xor_sync(0xffffffffu, contrib, 8);
    contrib += __shfl_xor_sync(0xffffffffu, contrib, 4);
    contrib += __shfl_xor_sync(0xffffffffu, contrib, 2);
    contrib += __shfl_xor_sync(0xffffffffu, contrib, 1);
    if (lane == 0) sred[warp] = contrib;
    __syncthreads();
    if (tid == 0) {
        float part = 0.0f;
        #pragma unroll
        for (int w = 0; w < NWARP; w++) part += sred[w];
        atomicAdd(&g_loss_sum, part);
        __threadfence();
        unsigned tk = atomicAdd(&g_ticket, 1u);
        s_flag = (tk == GRID - 1);
    }
    __syncthreads();
    if (!s_flag) return;

    // ================= last block: finalize =================
    float* st = (float*)(smem + FBUF_OFF);   // transition [576] (ring reusable now)
    float* sp = st + 576;                     // per-warp scan state [16][24]
    {
        int lnz = 0;
        for (int i = tid; i < TT * TT; i += NTH) {
            float v = trans[i];
            st[i] = v;
            lnz |= (v != 0.0f);
        }
        if (lnz) atomicOr(&s_nz, 1);
    }
    __syncthreads();

    if (!s_nz) {
        if (tid == 0) {
            if (has_loss) out[0] = -g_loss_sum / (float)BB;
            g_loss_sum = 0.0f;
            g_ticket = 0u;
        }
        return;
    }

    // generic nonzero-transition path (not taken for this dataset)
    {
        float wsum = 0.0f;
        float* msp = sp + warp * TT;
        for (int b = warp; b < BB; b += NWARP) {
            float sum = 0.0f;
            for (int s = lane; s < SS; s += 32) {
                const long idx = (long)b * SS + s;
                if (getmask(mask_raw, mt_, idx)) {
                    float v = emis[idx * TT + target[idx]];
                    if (s > 0) v += st[target[idx - 1] * TT + target[idx]];
                    sum += v;
                }
            }
            sum += __shfl_xor_sync(0xffffffffu, sum, 16);
            sum += __shfl_xor_sync(0xffffffffu, sum, 8);
            sum += __shfl_xor_sync(0xffffffffu, sum, 4);
            sum += __shfl_xor_sync(0xffffffffu, sum, 2);
            sum += __shfl_xor_sync(0xffffffffu, sum, 1);

            if (lane < TT) msp[lane] = emis[(long)b * SS * TT + lane];
            __syncwarp();
            for (int s = 1; s < SS; s++) {
                if (getmask(mask_raw, mt_, (long)b * SS + s)) {
                    float nv = 0.0f;
                    if (lane < TT) {
                        float mm = neg_inf();
                        #pragma unroll
                        for (int j = 0; j < TT; j++) mm = fmaxf(mm, msp[j] + st[j * TT + lane]);
                        float a = 0.0f;
                        #pragma unroll
                        for (int j = 0; j < TT; j++) a += __expf(msp[j] + st[j * TT + lane] - mm);
                        nv = emis[((long)b * SS + s) * TT + lane] + mm + __logf(a);
                    }
                    __syncwarp();
                    if (lane < TT) msp[lane] = nv;
                    __syncwarp();
                }
            }
            float e2 = (lane < TT) ? msp[lane] : neg_inf();
            float mm = e2;
            mm = fmaxf(mm, __shfl_xor_sync(0xffffffffu, mm, 16));
            mm = fmaxf(mm, __shfl_xor_sync(0xffffffffu, mm, 8));
            mm = fmaxf(mm, __shfl_xor_sync(0xffffffffu, mm, 4));
            mm = fmaxf(mm, __shfl_xor_sync(0xffffffffu, mm, 2));
            mm = fmaxf(mm, __shfl_xor_sync(0xffffffffu, mm, 1));
            float ex2 = (lane < TT) ? __expf(e2 - mm) : 0.0f;
            ex2 += __shfl_xor_sync(0xffffffffu, ex2, 16);
            ex2 += __shfl_xor_sync(0xffffffffu, ex2, 8);
            ex2 += __shfl_xor_sync(0xffffffffu, ex2, 4);
            ex2 += __shfl_xor_sync(0xffffffffu, ex2, 2);
            ex2 += __shfl_xor_sync(0xffffffffu, ex2, 1);
            if (lane == 0) wsum += sum - (mm + __logf(ex2));
        }
        if (lane == 0) atomicAdd(&s_tot, wsum);
    }
    __syncthreads();
    if (tid == 0) {
        if (has_loss) out[0] = -s_tot / (float)BB;
        g_loss_sum = 0.0f;
        g_ticket = 0u;
    }
}

// ---------------- launch ----------------
extern "C" void kernel_launch(void* const* d_in, const int* in_sizes, int n_in,
                              void* d_out, int out_size) {
    const float* feats  = (const float*)d_in[0];   // (B,S,H)
    const int*   target = (const int*)d_in[1];     // (B,S)
    const void*  mask   = d_in[2];                 // (B,S) dtype auto-detected
    const float* W      = (const float*)d_in[3];   // (T,H)
    const float* bias   = (const float*)d_in[4];   // (T,)
    const float* trans  = (const float*)d_in[5];   // (T,T)

    float* out = (float*)d_out;
    const int has_loss = (out_size == NROWS * TT + 1) ? 1 : 0;

    static int attr_set = 0;
    if (!attr_set) {
        cudaFuncSetAttribute(crf_kernel, cudaFuncAttributeMaxDynamicSharedMemorySize, SMEM_TOTAL);
        attr_set = 1;
    }

    crf_kernel<<<GRID, NTH, SMEM_TOTAL>>>(feats, W, bias, target, mask, trans, out, has_loss);
}

// round 13
// speedup vs baseline: 1.5661x; 1.2935x over previous
#include <cuda_runtime.h>
#include <cuda_bf16.h>
#include <math.h>
#include <stdint.h>

#define BB 64
#define SS 512
#define HH 1024
#define TT 24
#define NROWS (BB*SS)

#define GRID 148
#define NTH 512                    // 16 warps
#define NWARP 16
#define NCHUNK 64                  // K chunks of 16
#define NTILES (NROWS/16)          // 2048 tiles of 16 rows

// ---------------- device scratch ----------------
__device__ float    g_loss_sum;
__device__ unsigned g_ticket;
__device__ unsigned g_tile;
// pre-packed B fragments: [nt][chunk][lane] = {bh0,bh1,bl0,bl1}  (98304 B, L1-resident)
__device__ uint4    g_wfrag[3 * NCHUNK * 32];

__device__ __forceinline__ float neg_inf() { return __int_as_float(0xff800000); }

__device__ __forceinline__ uint32_t packbf(float x, float y) {
    uint32_t r; asm("cvt.rn.bf16x2.f32 %0, %1, %2;" : "=r"(r) : "f"(y), "f"(x)); return r;
}
__device__ __forceinline__ void split2f(float x, float y, uint32_t& hi, uint32_t& lo) {
    hi = packbf(x, y);
    float rx = x - __uint_as_float(hi << 16);
    float ry = y - __uint_as_float(hi & 0xFFFF0000u);
    lo = packbf(rx, ry);
}

__device__ __forceinline__ void mma16816(float* c, const uint32_t* a, uint32_t b0, uint32_t b1) {
    asm volatile("mma.sync.aligned.m16n8k16.row.col.f32.bf16.bf16.f32 "
        "{%0,%1,%2,%3}, {%4,%5,%6,%7}, {%8,%9}, {%0,%1,%2,%3};"
        : "+f"(c[0]), "+f"(c[1]), "+f"(c[2]), "+f"(c[3])
        : "r"(a[0]), "r"(a[1]), "r"(a[2]), "r"(a[3]), "r"(b0), "r"(b1));
}

__device__ __forceinline__ int getmask(const void* p, int mt, long i) {
    return mt == 0 ? (((const unsigned char*)p)[i] != 0)
         : mt == 1 ? (((const float*)p)[i] != 0.0f)
                   : (((const int*)p)[i] != 0);
}

// ================= prep: pack W into HMMA B-fragment layout =================
// Fragment (nt, c, lane): lane -> (n = nt*8 + lane>>2, kp = lane&3).
// With the A-side k-permutation (float4 natural order), HW slot b0 covers data
// k = c*16 + 4kp .. +1 and b1 covers k = c*16 + 4kp+2 .. +3.
__global__ void prep_kernel(const float* __restrict__ W) {
    const int idx = blockIdx.x * blockDim.x + threadIdx.x;   // 0 .. 6143
    const int nt = idx / (NCHUNK * 32);
    const int rem = idx % (NCHUNK * 32);
    const int c = rem >> 5, lane = rem & 31;
    const int n = nt * 8 + (lane >> 2), kp = lane & 3;
    const float* wr = W + n * HH + c * 16 + kp * 4;
    uint4 f;
    uint32_t lo;
    split2f(wr[0], wr[1], f.x, lo); f.z = lo;
    split2f(wr[2], wr[3], f.y, lo); f.w = lo;
    g_wfrag[idx] = f;
}

// ================= single fused persistent kernel =================
__global__ void __launch_bounds__(NTH, 1)
crf_kernel(const float* __restrict__ feats, const float* __restrict__ W,
           const float* __restrict__ bias, const int* __restrict__ target,
           const void* __restrict__ mask_raw, const float* __restrict__ trans,
           float* __restrict__ out, int has_loss) {
    __shared__ float sred[NWARP];
    __shared__ float st[TT * TT];       // generic path only
    __shared__ float sp[NWARP * TT];    // generic path only
    __shared__ int   s_flag, s_nz;
    __shared__ float s_tot;

    const int tid = threadIdx.x, warp = tid >> 5, lane = tid & 31;
    const int r = lane >> 2, kp = lane & 3;
    float* emis = out + has_loss;       // 4B-aligned only: scalar stores

    if (tid < NWARP) sred[tid] = 0.0f;
    if (tid == 0) { s_flag = 0; s_nz = 0; s_tot = 0.0f; }
    __syncthreads();

    const unsigned u0 = *(const unsigned*)mask_raw;
    const int mt_ = (u0 == 0x01010101u) ? 0 : ((u0 == 0x3F800000u) ? 1 : 2);

    const float4* f4g = (const float4*)feats;
    const uint4* wf_base = g_wfrag + lane;    // + nt*NCHUNK*32 + c*32
    float contrib = 0.0f;

    // ---- per-warp 16-row tile steal loop ----
    for (;;) {
        unsigned tile;
        if (lane == 0) tile = atomicAdd(&g_tile, 1u);
        tile = __shfl_sync(0xffffffffu, tile, 0);
        if (tile >= NTILES) break;
        const long row0 = (long)tile * 16;

        const long ra = (row0 + r)     * 256 + kp;   // float4 units
        const long rb = (row0 + r + 8) * 256 + kp;

        float acc[3][4];
        #pragma unroll
        for (int nt = 0; nt < 3; nt++)
            #pragma unroll
            for (int q = 0; q < 4; q++) acc[nt][q] = 0.0f;

        float4 fb0[2], fb1[2], fb2[2], fb3[2];

        #define LOADC(buf, c) do { \
            int _nc = (c) < NCHUNK ? (c) : (NCHUNK - 1); \
            buf[0] = __ldcs(f4g + ra + _nc * 4); \
            buf[1] = __ldcs(f4g + rb + _nc * 4); \
        } while (0)

        #define COMPUTE(buf, ch) do { \
            uint4 w0 = __ldg(wf_base + (ch) * 32); \
            uint4 w1 = __ldg(wf_base + (NCHUNK * 32) + (ch) * 32); \
            uint4 w2 = __ldg(wf_base + (2 * NCHUNK * 32) + (ch) * 32); \
            uint32_t ahi[4], alo[4]; \
            split2f(buf[0].x, buf[0].y, ahi[0], alo[0]); \
            split2f(buf[1].x, buf[1].y, ahi[1], alo[1]); \
            split2f(buf[0].z, buf[0].w, ahi[2], alo[2]); \
            split2f(buf[1].z, buf[1].w, ahi[3], alo[3]); \
            mma16816(acc[0], ahi, w0.x, w0.y); \
            mma16816(acc[0], ahi, w0.z, w0.w); \
            mma16816(acc[0], alo, w0.x, w0.y); \
            mma16816(acc[1], ahi, w1.x, w1.y); \
            mma16816(acc[1], ahi, w1.z, w1.w); \
            mma16816(acc[1], alo, w1.x, w1.y); \
            mma16816(acc[2], ahi, w2.x, w2.y); \
            mma16816(acc[2], ahi, w2.z, w2.w); \
            mma16816(acc[2], alo, w2.x, w2.y); \
        } while (0)

        LOADC(fb0, 0);
        LOADC(fb1, 1);
        LOADC(fb2, 2);
        #pragma unroll 4
        for (int c = 0; c < NCHUNK; c += 4) {
            LOADC(fb3, c + 3); COMPUTE(fb0, c);
            LOADC(fb0, c + 4); COMPUTE(fb1, c + 1);
            LOADC(fb1, c + 5); COMPUTE(fb2, c + 2);
            LOADC(fb2, c + 6); COMPUTE(fb3, c + 3);
        }
        #undef LOADC
        #undef COMPUTE

        // ---- epilogue: bias, scalar emission stores, quad-shfl LSE + target ----
        #pragma unroll
        for (int rr = 0; rr < 2; rr++) {
            const long row = row0 + rr * 8 + r;
            float e[6];
            float* eo = emis + row * TT;
            #pragma unroll
            for (int nt = 0; nt < 3; nt++) {
                const int col = nt * 8 + kp * 2;
                e[nt * 2]     = acc[nt][rr * 2]     + __ldg(bias + col);
                e[nt * 2 + 1] = acc[nt][rr * 2 + 1] + __ldg(bias + col + 1);
                eo[col]     = e[nt * 2];
                eo[col + 1] = e[nt * 2 + 1];
            }
            float mx = e[0];
            #pragma unroll
            for (int q = 1; q < 6; q++) mx = fmaxf(mx, e[q]);
            mx = fmaxf(mx, __shfl_xor_sync(0xffffffffu, mx, 1));
            mx = fmaxf(mx, __shfl_xor_sync(0xffffffffu, mx, 2));
            float ex = 0.0f;
            #pragma unroll
            for (int q = 0; q < 6; q++) ex += __expf(e[q] - mx);
            const int tg = target[row];
            float sc = 0.0f;
            #pragma unroll
            for (int nt = 0; nt < 3; nt++) {
                const int col = nt * 8 + kp * 2;
                sc += (tg == col) ? e[nt * 2] : 0.0f;
                sc += (tg == col + 1) ? e[nt * 2 + 1] : 0.0f;
            }
            ex += __shfl_xor_sync(0xffffffffu, ex, 1);
            sc += __shfl_xor_sync(0xffffffffu, sc, 1);
            ex += __shfl_xor_sync(0xffffffffu, ex, 2);
            sc += __shfl_xor_sync(0xffffffffu, sc, 2);
            if (kp == 0) {
                const float lse = mx + __logf(ex);
                const int s  = (int)(row & (SS - 1));
                const int mk = getmask(mask_raw, mt_, row);
                contrib += mk ? (sc - lse) : (s == 0 ? -lse : 0.0f);
            }
        }
    }

    // ---- warp + block reduce, ticket ----
    contrib += __shfl_xor_sync(0xffffffffu, contrib, 16);
    contrib += __shfl_xor_sync(0xffffffffu, contrib, 8);
    contrib += __shfl_xor_sync(0xffffffffu, contrib, 4);
    contrib += __shfl_xor_sync(0xffffffffu, contrib, 2);
    contrib += __shfl_xor_sync(0xffffffffu, contrib, 1);
    if (lane == 0) sred[warp] = contrib;
    __syncthreads();
    if (tid == 0) {
        float part = 0.0f;
        #pragma unroll
        for (int w = 0; w < NWARP; w++) part += sred[w];
        atomicAdd(&g_loss_sum, part);
        __threadfence();
        unsigned tk = atomicAdd(&g_ticket, 1u);
        s_flag = (tk == GRID - 1);
    }
    __syncthreads();
    if (!s_flag) return;

    // ================= last block: finalize =================
    {
        int lnz = 0;
        for (int i = tid; i < TT * TT; i += NTH) {
            float v = trans[i];
            st[i] = v;
            lnz |= (v != 0.0f);
        }
        if (lnz) atomicOr(&s_nz, 1);
    }
    __syncthreads();

    const unsigned u02 = *(const unsigned*)mask_raw;
    const int mt2 = (u02 == 0x01010101u) ? 0 : ((u02 == 0x3F800000u) ? 1 : 2);

    if (!s_nz) {
        if (tid == 0) {
            if (has_loss) out[0] = -g_loss_sum / (float)BB;
            g_loss_sum = 0.0f;
            g_ticket = 0u;
            g_tile = 0u;
        }
        return;
    }

    // generic nonzero-transition path (not taken for this dataset)
    {
        float wsum = 0.0f;
        float* msp = sp + warp * TT;
        for (int b = warp; b < BB; b += NWARP) {
            float sum = 0.0f;
            for (int s = lane; s < SS; s += 32) {
                const long idx = (long)b * SS + s;
                if (getmask(mask_raw, mt2, idx)) {
                    float v = emis[idx * TT + target[idx]];
                    if (s > 0) v += st[target[idx - 1] * TT + target[idx]];
                    sum += v;
                }
            }
            sum += __shfl_xor_sync(0xffffffffu, sum, 16);
            sum += __shfl_xor_sync(0xffffffffu, sum, 8);
            sum += __shfl_xor_sync(0xffffffffu, sum, 4);
            sum += __shfl_xor_sync(0xffffffffu, sum, 2);
            sum += __shfl_xor_sync(0xffffffffu, sum, 1);

            if (lane < TT) msp[lane] = emis[(long)b * SS * TT + lane];
            __syncwarp();
            for (int s = 1; s < SS; s++) {
                if (getmask(mask_raw, mt2, (long)b * SS + s)) {
                    float nv = 0.0f;
                    if (lane < TT) {
                        float mm = neg_inf();
                        #pragma unroll
                        for (int j = 0; j < TT; j++) mm = fmaxf(mm, msp[j] + st[j * TT + lane]);
                        float a = 0.0f;
                        #pragma unroll
                        for (int j = 0; j < TT; j++) a += __expf(msp[j] + st[j * TT + lane] - mm);
                        nv = emis[((long)b * SS + s) * TT + lane] + mm + __logf(a);
                    }
                    __syncwarp();
                    if (lane < TT) msp[lane] = nv;
                    __syncwarp();
                }
            }
            float e2 = (lane < TT) ? msp[lane] : neg_inf();
            float mm = e2;
            mm = fmaxf(mm, __shfl_xor_sync(0xffffffffu, mm, 16));
            mm = fmaxf(mm, __shfl_xor_sync(0xffffffffu, mm, 8));
            mm = fmaxf(mm, __shfl_xor_sync(0xffffffffu, mm, 4));
            mm = fmaxf(mm, __shfl_xor_sync(0xffffffffu, mm, 2));
            mm = fmaxf(mm, __shfl_xor_sync(0xffffffffu, mm, 1));
            float ex2 = (lane < TT) ? __expf(e2 - mm) : 0.0f;
            ex2 += __shfl_xor_sync(0xffffffffu, ex2, 16);
            ex2 += __shfl_xor_sync(0xffffffffu, ex2, 8);
            ex2 += __shfl_xor_sync(0xffffffffu, ex2, 4);
            ex2 += __shfl_xor_sync(0xffffffffu, ex2, 2);
            ex2 += __shfl_xor_sync(0xffffffffu, ex2, 1);
            if (lane == 0) wsum += sum - (mm + __logf(ex2));
        }
        if (lane == 0) atomicAdd(&s_tot, wsum);
    }
    __syncthreads();
    if (tid == 0) {
        if (has_loss) out[0] = -s_tot / (float)BB;
        g_loss_sum = 0.0f;
        g_ticket = 0u;
        g_tile = 0u;
    }
}

// ---------------- launch ----------------
extern "C" void kernel_launch(void* const* d_in, const int* in_sizes, int n_in,
                              void* d_out, int out_size) {
    const float* feats  = (const float*)d_in[0];   // (B,S,H)
    const int*   target = (const int*)d_in[1];     // (B,S)
    const void*  mask   = d_in[2];                 // (B,S) dtype auto-detected
    const float* W      = (const float*)d_in[3];   // (T,H)
    const float* bias   = (const float*)d_in[4];   // (T,)
    const float* trans  = (const float*)d_in[5];   // (T,T)

    float* out = (float*)d_out;
    const int has_loss = (out_size == NROWS * TT + 1) ? 1 : 0;

    prep_kernel<<<24, 256>>>(W);
    crf_kernel<<<GRID, NTH>>>(feats, W, bias, target, mask, trans, out, has_loss);
}